// round 2
// baseline (speedup 1.0000x reference)
#include <cuda_runtime.h>
#include <math.h>
#include <stdint.h>

// ---------------- problem constants (fixed by setup_inputs) ----------------
#define T_TOK 32768
#define HID   384
#define NGATE 1536
#define NSEQ  16

// ---------------- scratch (static device arrays; no allocation) ------------
__device__ float g_X [(size_t)T_TOK * HID];    // [T,384] LSTM input (enc|prev)
__device__ float g_gx[(size_t)T_TOK * NGATE];  // [T,1536] input gate preacts
__device__ float g_y1[(size_t)T_TOK * HID];    // tanh(extra)@wh2^T
__device__ float g_x1[(size_t)T_TOK * HID];    // tanh(lstm)@wh1^T

__device__ __forceinline__ float sigm(float x) { return 1.f / (1.f + expf(-x)); }

// ============================================================================
// prepare: build X = [encoded | prev_label_embedding]
// ============================================================================
__global__ void prepare_kernel(const float* __restrict__ enc,
                               const int*   __restrict__ forced,
                               const int*   __restrict__ lens,
                               const float* __restrict__ emb,
                               const float* __restrict__ initt)
{
    int idx = blockIdx.x * blockDim.x + threadIdx.x;   // T*96 float4 slots
    if (idx >= T_TOK * 96) return;
    int tok = idx / 96;
    int q   = idx - tok * 96;

    float4 v;
    if (q < 64) {
        v = ((const float4*)enc)[(size_t)tok * 64 + q];
    } else {
        bool is64 = (lens[1] == 0);        // int64 layout heuristic (len!=0 always)
        bool is_start = false;
        int srt = 0;
        #pragma unroll
        for (int i = 0; i < NSEQ; i++) {
            if (tok == srt) is_start = true;
            srt += lens[is64 ? 2 * i : i];
        }
        if (is_start) {
            v = ((const float4*)initt)[q - 64];
        } else {
            int fi = forced[is64 ? 2 * (tok - 1) : (tok - 1)];
            v = ((const float4*)(emb + (size_t)fi * 128))[q - 64];
        }
    }
    ((float4*)g_X)[(size_t)tok * 96 + q] = v;
}

// ============================================================================
// SGEMM: C[M,N] = opA(A)[M,K] @ B[N,K]^T  (+bias / +fusion epilogue)
// BM=BN=128, BK=16, 256 threads, 8x8 micro-tile. M,N,K all divide tiles here.
// ============================================================================
#define BM 128
#define BN 128
#define BK 16

#define MODE_BIAS   0   // C = A@B^T + bias          (gx)
#define MODE_TANHA  1   // C = tanh(A)@B^T           (x1 / y1)
#define MODE_FUSION 2   // pre = [A|A2]@B^T ; C = fusion(pre, E1=lstm, E2=extra)

__device__ __forceinline__ float fuse_elem(float pre, float L, float Ev)
{
    float f  = 1.f / (1.f + expf(-pre));
    float x0 = tanhf(L);
    float y0 = tanhf(Ev);
    float x2 = f * x0 + L;
    float y2 = (1.f - f) * y0 + Ev;
    return f * x2 + (1.f - f) * y2;
}

template<int MODE>
__global__ __launch_bounds__(256)
void sgemm_k(const float* __restrict__ A, const float* __restrict__ A2,
             const float* __restrict__ B, const float* __restrict__ bias,
             float* __restrict__ C,
             const float* __restrict__ E1, const float* __restrict__ E2,
             int N, int K)
{
    __shared__ float As[BK][BM + 4];
    __shared__ float Bs[BK][BN + 4];

    int tid = threadIdx.x;
    int m0  = blockIdx.y * BM;
    int n0  = blockIdx.x * BN;
    int tx  = tid & 15;
    int ty  = tid >> 4;

    float acc[8][8];
    #pragma unroll
    for (int i = 0; i < 8; i++)
        #pragma unroll
        for (int j = 0; j < 8; j++) acc[i][j] = 0.f;

    for (int k0 = 0; k0 < K; k0 += BK) {
        // ---- load A tile (transpose to As[k][m]) ----
        #pragma unroll
        for (int i = 0; i < 2; i++) {
            int f  = tid + i * 256;        // 0..511 float4s
            int r  = f >> 2;               // row in tile
            int kq = f & 3;                // which float4 along k
            const float* src;
            if (MODE == MODE_FUSION) {
                src = (k0 < 384) ? (A  + (size_t)(m0 + r) * 384 + k0)
                                 : (A2 + (size_t)(m0 + r) * 384 + (k0 - 384));
            } else {
                src = A + (size_t)(m0 + r) * K + k0;
            }
            float4 v = *(const float4*)(src + kq * 4);
            if (MODE == MODE_TANHA) {
                v.x = tanhf(v.x); v.y = tanhf(v.y);
                v.z = tanhf(v.z); v.w = tanhf(v.w);
            }
            As[kq * 4 + 0][r] = v.x; As[kq * 4 + 1][r] = v.y;
            As[kq * 4 + 2][r] = v.z; As[kq * 4 + 3][r] = v.w;
        }
        // ---- load B tile (transpose to Bs[k][n]) ----
        #pragma unroll
        for (int i = 0; i < 2; i++) {
            int f  = tid + i * 256;
            int r  = f >> 2;
            int kq = f & 3;
            float4 v = *(const float4*)(B + (size_t)(n0 + r) * K + k0 + kq * 4);
            Bs[kq * 4 + 0][r] = v.x; Bs[kq * 4 + 1][r] = v.y;
            Bs[kq * 4 + 2][r] = v.z; Bs[kq * 4 + 3][r] = v.w;
        }
        __syncthreads();

        #pragma unroll
        for (int kk = 0; kk < BK; kk++) {
            float a[8], b[8];
            float4 a0 = *(const float4*)&As[kk][ty * 8];
            float4 a1 = *(const float4*)&As[kk][ty * 8 + 4];
            float4 b0 = *(const float4*)&Bs[kk][tx * 8];
            float4 b1 = *(const float4*)&Bs[kk][tx * 8 + 4];
            a[0]=a0.x; a[1]=a0.y; a[2]=a0.z; a[3]=a0.w;
            a[4]=a1.x; a[5]=a1.y; a[6]=a1.z; a[7]=a1.w;
            b[0]=b0.x; b[1]=b0.y; b[2]=b0.z; b[3]=b0.w;
            b[4]=b1.x; b[5]=b1.y; b[6]=b1.z; b[7]=b1.w;
            #pragma unroll
            for (int i = 0; i < 8; i++)
                #pragma unroll
                for (int j = 0; j < 8; j++)
                    acc[i][j] = fmaf(a[i], b[j], acc[i][j]);
        }
        __syncthreads();
    }

    // ---- epilogue ----
    #pragma unroll
    for (int i = 0; i < 8; i++) {
        size_t m = (size_t)(m0 + ty * 8 + i);
        #pragma unroll
        for (int q = 0; q < 2; q++) {
            int n = n0 + tx * 8 + q * 4;
            float r0 = acc[i][q * 4 + 0], r1 = acc[i][q * 4 + 1];
            float r2 = acc[i][q * 4 + 2], r3 = acc[i][q * 4 + 3];
            if (MODE == MODE_BIAS) {
                float4 bv = *(const float4*)(bias + n);
                r0 += bv.x; r1 += bv.y; r2 += bv.z; r3 += bv.w;
            }
            if (MODE == MODE_FUSION) {
                float4 L = *(const float4*)(E1 + m * 384 + n);
                float4 E = *(const float4*)(E2 + m * 384 + n);
                r0 = fuse_elem(r0, L.x, E.x); r1 = fuse_elem(r1, L.y, E.y);
                r2 = fuse_elem(r2, L.z, E.z); r3 = fuse_elem(r3, L.w, E.w);
            }
            float4 ov = make_float4(r0, r1, r2, r3);
            *(float4*)(C + m * N + n) = ov;
        }
    }
}

// ============================================================================
// LSTM scan: 16 sequences x 8-CTA clusters, 384 thr/CTA.
// CTA rank r owns hidden units [r*48, r*48+48) => 192 gate rows.
// Each thread: 1 row, half of K (192 elems): 96 W in regs + 96 W in smem.
// h exchanged per step via st.shared::cluster into peers' double-buffered h.
// ============================================================================
#define SCAN_THREADS 384
#define SCAN_WS_FLOATS (24 * 384 * 4)                 // 36864 floats
#define SCAN_SMEM_BYTES ((SCAN_WS_FLOATS + 2 * HID + 256) * 4)

__global__ void __cluster_dims__(8, 1, 1) __launch_bounds__(SCAN_THREADS, 1)
lstm_scan_kernel(const float* __restrict__ gx, const float* __restrict__ W_hh,
                 const float* __restrict__ b_hh, const int* __restrict__ lens,
                 float* __restrict__ lstm)
{
    extern __shared__ float sm[];
    float* Ws     = sm;                          // [24][384] float4-elems
    float* h_full = sm + SCAN_WS_FLOATS;         // double-buffered [2][384]
    float* gatesv = h_full + 2 * HID;            // [192]

    int t = threadIdx.x;
    uint32_t rank;
    asm("mov.u32 %0, %%cluster_ctarank;" : "=r"(rank));
    int seq = blockIdx.x >> 3;

    bool is64 = (lens[1] == 0);
    int start = 0;
    for (int i = 0; i < seq; i++) start += lens[is64 ? 2 * i : i];
    int len = lens[is64 ? 2 * seq : seq];

    int row_local = t >> 1;                 // 0..191
    int khalf     = t & 1;                  // which K half
    int gate      = row_local / 48;         // 0..3 (i,f,g,o)
    int unit      = row_local - gate * 48;  // 0..47
    int grow      = gate * HID + (int)rank * 48 + unit;
    int kb        = khalf * 192;

    // ---- stage W_hh slice: 96 elems -> registers, 96 elems -> smem ----
    float4 wreg[24];
    {
        const float4* wsrc = (const float4*)(W_hh + (size_t)grow * HID + kb);
        #pragma unroll
        for (int j = 0; j < 24; j++) wreg[j] = wsrc[j];
        float4* Ws4w = (float4*)Ws;
        #pragma unroll
        for (int j = 0; j < 24; j++) Ws4w[j * 384 + t] = wsrc[24 + j];
    }
    float bh = b_hh[grow];
    h_full[t] = 0.f;
    h_full[HID + t] = 0.f;
    float c = 0.f;
    __syncthreads();

    const float*  gxp  = gx + (size_t)start * NGATE + grow;
    float*        lout = lstm + (size_t)start * HID + (size_t)rank * 48 + (t < 48 ? t : 0);
    const float4* Ws4  = (const float4*)Ws;

    int par = 0;
    float gxv = __ldg(gxp);                 // prefetch step 0
    for (int step = 0; step < len; step++) {
        // prefetch next token's gx early to hide L2 latency behind the dot
        float gxn = 0.f;
        if (step + 1 < len) gxn = __ldg(gxp + (size_t)(step + 1) * NGATE);

        const float4* h4 = (const float4*)(h_full + par * HID + kb);
        float acc = 0.f;
        #pragma unroll
        for (int j = 0; j < 24; j++) {      // register-resident W
            float4 hv = h4[j]; float4 wv = wreg[j];
            acc = fmaf(wv.x, hv.x, acc); acc = fmaf(wv.y, hv.y, acc);
            acc = fmaf(wv.z, hv.z, acc); acc = fmaf(wv.w, hv.w, acc);
        }
        #pragma unroll
        for (int j = 0; j < 24; j++) {      // smem-resident W
            float4 hv = h4[24 + j]; float4 wv = Ws4[j * 384 + t];
            acc = fmaf(wv.x, hv.x, acc); acc = fmaf(wv.y, hv.y, acc);
            acc = fmaf(wv.z, hv.z, acc); acc = fmaf(wv.w, hv.w, acc);
        }
        float other = __shfl_xor_sync(0xffffffffu, acc, 1);
        if (khalf == 0) gatesv[row_local] = acc + other + gxv + bh;
        __syncthreads();

        if (t < 48) {
            float gi = gatesv[t];
            float gf = gatesv[48 + t];
            float gg = gatesv[96 + t];
            float go = gatesv[144 + t];
            c = sigm(gf) * c + sigm(gi) * tanhf(gg);
            float h = sigm(go) * tanhf(c);
            lout[(size_t)step * HID] = h;
            // broadcast h into the (par^1) buffer of every CTA in the cluster
            float* dst = &h_full[(par ^ 1) * HID + (int)rank * 48 + t];
            uint32_t la;
            asm("{ .reg .u64 u; cvta.to.shared.u64 u, %1; cvt.u32.u64 %0, u; }"
                : "=r"(la) : "l"(dst));
            #pragma unroll
            for (int r2 = 0; r2 < 8; r2++) {
                uint32_t ra;
                asm("mapa.shared::cluster.u32 %0, %1, %2;" : "=r"(ra) : "r"(la), "r"(r2));
                asm volatile("st.shared::cluster.f32 [%0], %1;" :: "r"(ra), "f"(h) : "memory");
            }
        }
        // cluster barrier: release writes, acquire peers' h
        asm volatile("barrier.cluster.arrive.aligned;" ::: "memory");
        asm volatile("barrier.cluster.wait.aligned;" ::: "memory");
        par ^= 1;
        gxv = gxn;
    }
}

// ============================================================================
// launch
// ============================================================================
extern "C" void kernel_launch(void* const* d_in, const int* in_sizes, int n_in,
                              void* d_out, int out_size)
{
    const float* enc    = (const float*)d_in[0];
    const float* extra  = (const float*)d_in[1];
    const int*   forced = (const int*)  d_in[2];
    const int*   lens   = (const int*)  d_in[3];
    const float* emb    = (const float*)d_in[4];
    const float* initt  = (const float*)d_in[5];
    const float* W_ih   = (const float*)d_in[6];
    const float* W_hh   = (const float*)d_in[7];
    const float* b_ih   = (const float*)d_in[8];
    const float* b_hh   = (const float*)d_in[9];
    const float* wh1    = (const float*)d_in[10];
    const float* wh2    = (const float*)d_in[11];
    const float* wsig   = (const float*)d_in[12];

    float* out    = (float*)d_out;
    float* fusion = out;                               // [T,384]
    float* lstm   = out + (size_t)T_TOK * HID;         // [T,384]

    float *Xp, *gxp, *y1p, *x1p;
    cudaGetSymbolAddress((void**)&Xp,  g_X);
    cudaGetSymbolAddress((void**)&gxp, g_gx);
    cudaGetSymbolAddress((void**)&y1p, g_y1);
    cudaGetSymbolAddress((void**)&x1p, g_x1);

    cudaFuncSetAttribute(lstm_scan_kernel,
                         cudaFuncAttributeMaxDynamicSharedMemorySize,
                         SCAN_SMEM_BYTES);

    // 1) build X
    prepare_kernel<<<(T_TOK * 96 + 255) / 256, 256>>>(enc, forced, lens, emb, initt);

    // 2) gx = X @ W_ih^T + b_ih   [T,1536]
    sgemm_k<MODE_BIAS><<<dim3(NGATE / BN, T_TOK / BM), 256>>>(
        Xp, nullptr, W_ih, b_ih, gxp, nullptr, nullptr, NGATE, HID);

    // 3) LSTM scan -> lstm (second half of d_out)
    lstm_scan_kernel<<<128, SCAN_THREADS, SCAN_SMEM_BYTES>>>(gxp, W_hh, b_hh, lens, lstm);

    // 4) y1 = tanh(extra) @ wh2^T
    sgemm_k<MODE_TANHA><<<dim3(HID / BN, T_TOK / BM), 256>>>(
        extra, nullptr, wh2, nullptr, y1p, nullptr, nullptr, HID, HID);

    // 5) x1 = tanh(lstm) @ wh1^T
    sgemm_k<MODE_TANHA><<<dim3(HID / BN, T_TOK / BM), 256>>>(
        lstm, nullptr, wh1, nullptr, x1p, nullptr, nullptr, HID, HID);

    // 6) f = sigmoid([x1|y1] @ Wsig^T); fusion epilogue -> first half of d_out
    sgemm_k<MODE_FUSION><<<dim3(HID / BN, T_TOK / BM), 256>>>(
        x1p, y1p, wsig, nullptr, fusion, lstm, extra, HID, 2 * HID);
}

// round 3
// speedup vs baseline: 1.3461x; 1.3461x over previous
#include <cuda_runtime.h>
#include <math.h>
#include <stdint.h>

// ---------------- problem constants (fixed by setup_inputs) ----------------
#define T_TOK 32768
#define HID   384
#define NGATE 1536
#define NSEQ  16

// ---------------- scratch (static device arrays; no allocation) ------------
__device__ float g_X [(size_t)T_TOK * HID];    // [T,384] LSTM input (enc|prev)
__device__ float g_gx[(size_t)T_TOK * NGATE];  // [T,1536] input gate preacts
__device__ float g_y1[(size_t)T_TOK * HID];    // tanh(extra)@wh2^T
__device__ float g_x1[(size_t)T_TOK * HID];    // tanh(lstm)@wh1^T

__device__ __forceinline__ float sigm(float x) { return 1.f / (1.f + expf(-x)); }

// ============================================================================
// prepare: build X = [encoded | prev_label_embedding]
// ============================================================================
__global__ void prepare_kernel(const float* __restrict__ enc,
                               const int*   __restrict__ forced,
                               const int*   __restrict__ lens,
                               const float* __restrict__ emb,
                               const float* __restrict__ initt)
{
    int idx = blockIdx.x * blockDim.x + threadIdx.x;   // T*96 float4 slots
    if (idx >= T_TOK * 96) return;
    int tok = idx / 96;
    int q   = idx - tok * 96;

    float4 v;
    if (q < 64) {
        v = ((const float4*)enc)[(size_t)tok * 64 + q];
    } else {
        bool is64 = (lens[1] == 0);        // int64 layout heuristic (len!=0 always)
        bool is_start = false;
        int srt = 0;
        #pragma unroll
        for (int i = 0; i < NSEQ; i++) {
            if (tok == srt) is_start = true;
            srt += lens[is64 ? 2 * i : i];
        }
        if (is_start) {
            v = ((const float4*)initt)[q - 64];
        } else {
            int fi = forced[is64 ? 2 * (tok - 1) : (tok - 1)];
            v = ((const float4*)(emb + (size_t)fi * 128))[q - 64];
        }
    }
    ((float4*)g_X)[(size_t)tok * 96 + q] = v;
}

// ============================================================================
// SGEMM: C[M,N] = opA(A)[M,K] @ B[N,K]^T  (+bias / +fusion epilogue)
// BM=BN=128, BK=16, 256 threads, 8x8 micro-tile. M,N,K all divide tiles here.
// ============================================================================
#define BM 128
#define BN 128
#define BK 16

#define MODE_BIAS   0   // C = A@B^T + bias          (gx)
#define MODE_TANHA  1   // C = tanh(A)@B^T           (x1 / y1)
#define MODE_FUSION 2   // pre = [A|A2]@B^T ; C = fusion(pre, E1=lstm, E2=extra)

__device__ __forceinline__ float fuse_elem(float pre, float L, float Ev)
{
    float f  = 1.f / (1.f + expf(-pre));
    float x0 = tanhf(L);
    float y0 = tanhf(Ev);
    float x2 = f * x0 + L;
    float y2 = (1.f - f) * y0 + Ev;
    return f * x2 + (1.f - f) * y2;
}

template<int MODE>
__global__ __launch_bounds__(256)
void sgemm_k(const float* __restrict__ A, const float* __restrict__ A2,
             const float* __restrict__ B, const float* __restrict__ bias,
             float* __restrict__ C,
             const float* __restrict__ E1, const float* __restrict__ E2,
             int N, int K)
{
    __shared__ float As[BK][BM + 4];
    __shared__ float Bs[BK][BN + 4];

    int tid = threadIdx.x;
    int m0  = blockIdx.y * BM;
    int n0  = blockIdx.x * BN;
    int tx  = tid & 15;
    int ty  = tid >> 4;

    float acc[8][8];
    #pragma unroll
    for (int i = 0; i < 8; i++)
        #pragma unroll
        for (int j = 0; j < 8; j++) acc[i][j] = 0.f;

    for (int k0 = 0; k0 < K; k0 += BK) {
        // ---- load A tile (transpose to As[k][m]) ----
        #pragma unroll
        for (int i = 0; i < 2; i++) {
            int f  = tid + i * 256;        // 0..511 float4s
            int r  = f >> 2;               // row in tile
            int kq = f & 3;                // which float4 along k
            const float* src;
            if (MODE == MODE_FUSION) {
                src = (k0 < 384) ? (A  + (size_t)(m0 + r) * 384 + k0)
                                 : (A2 + (size_t)(m0 + r) * 384 + (k0 - 384));
            } else {
                src = A + (size_t)(m0 + r) * K + k0;
            }
            float4 v = *(const float4*)(src + kq * 4);
            if (MODE == MODE_TANHA) {
                v.x = tanhf(v.x); v.y = tanhf(v.y);
                v.z = tanhf(v.z); v.w = tanhf(v.w);
            }
            As[kq * 4 + 0][r] = v.x; As[kq * 4 + 1][r] = v.y;
            As[kq * 4 + 2][r] = v.z; As[kq * 4 + 3][r] = v.w;
        }
        // ---- load B tile (transpose to Bs[k][n]) ----
        #pragma unroll
        for (int i = 0; i < 2; i++) {
            int f  = tid + i * 256;
            int r  = f >> 2;
            int kq = f & 3;
            float4 v = *(const float4*)(B + (size_t)(n0 + r) * K + k0 + kq * 4);
            Bs[kq * 4 + 0][r] = v.x; Bs[kq * 4 + 1][r] = v.y;
            Bs[kq * 4 + 2][r] = v.z; Bs[kq * 4 + 3][r] = v.w;
        }
        __syncthreads();

        #pragma unroll
        for (int kk = 0; kk < BK; kk++) {
            float a[8], b[8];
            float4 a0 = *(const float4*)&As[kk][ty * 8];
            float4 a1 = *(const float4*)&As[kk][ty * 8 + 4];
            float4 b0 = *(const float4*)&Bs[kk][tx * 8];
            float4 b1 = *(const float4*)&Bs[kk][tx * 8 + 4];
            a[0]=a0.x; a[1]=a0.y; a[2]=a0.z; a[3]=a0.w;
            a[4]=a1.x; a[5]=a1.y; a[6]=a1.z; a[7]=a1.w;
            b[0]=b0.x; b[1]=b0.y; b[2]=b0.z; b[3]=b0.w;
            b[4]=b1.x; b[5]=b1.y; b[6]=b1.z; b[7]=b1.w;
            #pragma unroll
            for (int i = 0; i < 8; i++)
                #pragma unroll
                for (int j = 0; j < 8; j++)
                    acc[i][j] = fmaf(a[i], b[j], acc[i][j]);
        }
        __syncthreads();
    }

    // ---- epilogue ----
    #pragma unroll
    for (int i = 0; i < 8; i++) {
        size_t m = (size_t)(m0 + ty * 8 + i);
        #pragma unroll
        for (int q = 0; q < 2; q++) {
            int n = n0 + tx * 8 + q * 4;
            float r0 = acc[i][q * 4 + 0], r1 = acc[i][q * 4 + 1];
            float r2 = acc[i][q * 4 + 2], r3 = acc[i][q * 4 + 3];
            if (MODE == MODE_BIAS) {
                float4 bv = *(const float4*)(bias + n);
                r0 += bv.x; r1 += bv.y; r2 += bv.z; r3 += bv.w;
            }
            if (MODE == MODE_FUSION) {
                float4 L = *(const float4*)(E1 + m * 384 + n);
                float4 E = *(const float4*)(E2 + m * 384 + n);
                r0 = fuse_elem(r0, L.x, E.x); r1 = fuse_elem(r1, L.y, E.y);
                r2 = fuse_elem(r2, L.z, E.z); r3 = fuse_elem(r3, L.w, E.w);
            }
            float4 ov = make_float4(r0, r1, r2, r3);
            *(float4*)(C + m * N + n) = ov;
        }
    }
}

// ============================================================================
// LSTM scan v2: 16 sequences x 8-CTA clusters, 384 thr/CTA.
// CTA rank r owns hidden units [r*48, r*48+48) => 192 gate rows.
// Thread t: kslice = t&7 (48 k-elems), rowblock = t>>3 (4 rows).
//   -> 4 independent acc chains, h loads amortized 4x, W: 96 reg + 96 smem.
// h vector kept in padded layout (52 floats per 48-chunk) for conflict-free
// strided reads. 8-lane shfl reduction -> one STS.128 per rowblock.
// h exchanged per step via st.shared::cluster into peers' double buffer.
// ============================================================================
#define SCAN_THREADS 384
#define WS_FLOATS (24 * 384 * 4)     // 96 floats/thread of W in smem
#define HPAD 416                     // 8 chunks * 52 floats
#define SCAN_SMEM_BYTES ((WS_FLOATS + 2 * HPAD + 192 + 64) * 4)

__global__ void __cluster_dims__(8, 1, 1) __launch_bounds__(SCAN_THREADS, 1)
lstm_scan_kernel(const float* __restrict__ gx, const float* __restrict__ W_hh,
                 const float* __restrict__ b_hh, const int* __restrict__ lens,
                 float* __restrict__ lstm)
{
    extern __shared__ float sm[];
    float4* Ws4    = (float4*)sm;                 // [24][384] float4
    float*  h_pad  = sm + WS_FLOATS;              // [2][HPAD]
    float*  gatesv = h_pad + 2 * HPAD;            // [192]

    int t = threadIdx.x;
    uint32_t rank;
    asm("mov.u32 %0, %%cluster_ctarank;" : "=r"(rank));
    int seq = blockIdx.x >> 3;

    bool is64 = (lens[1] == 0);
    int start = 0;
    for (int i = 0; i < seq; i++) start += lens[is64 ? 2 * i : i];
    int len = lens[is64 ? 2 * seq : seq];

    int ks    = t & 7;        // k-slice 0..7 -> k in [ks*48, ks*48+48)
    int rb    = t >> 3;       // row block 0..47 -> local rows rb*4..rb*4+3
    int kbase = ks * 48;

    // ---- stage W: rows 0,1 of the block -> registers; rows 2,3 -> smem ----
    float4 w0[12], w1[12];
    #pragma unroll
    for (int i = 0; i < 4; i++) {
        int lr   = rb * 4 + i;
        int gate = lr / 48;
        int unit = lr - gate * 48;
        int grow = gate * HID + (int)rank * 48 + unit;
        const float4* src = (const float4*)(W_hh + (size_t)grow * HID + kbase);
        if (i == 0) {
            #pragma unroll
            for (int j = 0; j < 12; j++) w0[j] = src[j];
        } else if (i == 1) {
            #pragma unroll
            for (int j = 0; j < 12; j++) w1[j] = src[j];
        } else {
            #pragma unroll
            for (int j = 0; j < 12; j++) Ws4[((i - 2) * 12 + j) * 384 + t] = src[j];
        }
    }

    // ---- pointwise-thread state (threads 0..47 handle hidden unit t) ----
    float c = 0.f, bh0 = 0.f, bh1 = 0.f, bh2 = 0.f, bh3 = 0.f;
    const float* gxp  = gx;
    float*       lout = lstm;
    if (t < 48) {
        int u = (int)rank * 48 + t;
        bh0 = b_hh[u];  bh1 = b_hh[HID + u];
        bh2 = b_hh[2 * HID + u];  bh3 = b_hh[3 * HID + u];
        gxp  = gx   + (size_t)start * NGATE + u;
        lout = lstm + (size_t)start * HID   + u;
    }

    for (int i = t; i < 2 * HPAD; i += SCAN_THREADS) h_pad[i] = 0.f;
    __syncthreads();

    int par = 0;
    for (int step = 0; step < len; step++) {
        // issue gx loads for THIS step up front; latency hides under the dot
        float g0 = 0.f, g1 = 0.f, g2 = 0.f, g3 = 0.f;
        if (t < 48) {
            const float* gp = gxp + (size_t)step * NGATE;
            g0 = __ldg(gp);
            g1 = __ldg(gp + HID);
            g2 = __ldg(gp + 2 * HID);
            g3 = __ldg(gp + 3 * HID);
        }

        const float4* h4 = (const float4*)(h_pad + par * HPAD + ks * 52);
        float a0 = 0.f, a1 = 0.f, a2 = 0.f, a3 = 0.f;
        #pragma unroll
        for (int j = 0; j < 12; j++) {
            float4 hv = h4[j];
            float4 v0 = w0[j];
            float4 v1 = w1[j];
            float4 v2 = Ws4[j * 384 + t];
            float4 v3 = Ws4[(12 + j) * 384 + t];
            a0 = fmaf(v0.x, hv.x, a0); a0 = fmaf(v0.y, hv.y, a0);
            a0 = fmaf(v0.z, hv.z, a0); a0 = fmaf(v0.w, hv.w, a0);
            a1 = fmaf(v1.x, hv.x, a1); a1 = fmaf(v1.y, hv.y, a1);
            a1 = fmaf(v1.z, hv.z, a1); a1 = fmaf(v1.w, hv.w, a1);
            a2 = fmaf(v2.x, hv.x, a2); a2 = fmaf(v2.y, hv.y, a2);
            a2 = fmaf(v2.z, hv.z, a2); a2 = fmaf(v2.w, hv.w, a2);
            a3 = fmaf(v3.x, hv.x, a3); a3 = fmaf(v3.y, hv.y, a3);
            a3 = fmaf(v3.z, hv.z, a3); a3 = fmaf(v3.w, hv.w, a3);
        }
        // reduce across the 8 k-slices (lanes l, l^1, l^2, l^4)
        a0 += __shfl_xor_sync(0xffffffffu, a0, 1);
        a1 += __shfl_xor_sync(0xffffffffu, a1, 1);
        a2 += __shfl_xor_sync(0xffffffffu, a2, 1);
        a3 += __shfl_xor_sync(0xffffffffu, a3, 1);
        a0 += __shfl_xor_sync(0xffffffffu, a0, 2);
        a1 += __shfl_xor_sync(0xffffffffu, a1, 2);
        a2 += __shfl_xor_sync(0xffffffffu, a2, 2);
        a3 += __shfl_xor_sync(0xffffffffu, a3, 2);
        a0 += __shfl_xor_sync(0xffffffffu, a0, 4);
        a1 += __shfl_xor_sync(0xffffffffu, a1, 4);
        a2 += __shfl_xor_sync(0xffffffffu, a2, 4);
        a3 += __shfl_xor_sync(0xffffffffu, a3, 4);
        if (ks == 0) *(float4*)&gatesv[rb * 4] = make_float4(a0, a1, a2, a3);
        __syncthreads();

        if (t < 48) {
            float gi = gatesv[t]         + g0 + bh0;
            float gf = gatesv[48 + t]    + g1 + bh1;
            float gg = gatesv[96 + t]    + g2 + bh2;
            float go = gatesv[144 + t]   + g3 + bh3;
            c = sigm(gf) * c + sigm(gi) * tanhf(gg);
            float h = sigm(go) * tanhf(c);
            lout[(size_t)step * HID] = h;
            // broadcast h into the (par^1) buffer of every CTA (padded slot)
            float* dst = &h_pad[(par ^ 1) * HPAD + (int)rank * 52 + t];
            uint32_t la;
            asm("{ .reg .u64 u; cvta.to.shared.u64 u, %1; cvt.u32.u64 %0, u; }"
                : "=r"(la) : "l"(dst));
            #pragma unroll
            for (int r2 = 0; r2 < 8; r2++) {
                uint32_t ra;
                asm("mapa.shared::cluster.u32 %0, %1, %2;" : "=r"(ra) : "r"(la), "r"(r2));
                asm volatile("st.shared::cluster.f32 [%0], %1;" :: "r"(ra), "f"(h) : "memory");
            }
        }
        // cluster barrier: release h writes, acquire peers' h
        asm volatile("barrier.cluster.arrive.aligned;" ::: "memory");
        asm volatile("barrier.cluster.wait.aligned;" ::: "memory");
        par ^= 1;
    }
}

// ============================================================================
// launch
// ============================================================================
extern "C" void kernel_launch(void* const* d_in, const int* in_sizes, int n_in,
                              void* d_out, int out_size)
{
    const float* enc    = (const float*)d_in[0];
    const float* extra  = (const float*)d_in[1];
    const int*   forced = (const int*)  d_in[2];
    const int*   lens   = (const int*)  d_in[3];
    const float* emb    = (const float*)d_in[4];
    const float* initt  = (const float*)d_in[5];
    const float* W_ih   = (const float*)d_in[6];
    const float* W_hh   = (const float*)d_in[7];
    const float* b_ih   = (const float*)d_in[8];
    const float* b_hh   = (const float*)d_in[9];
    const float* wh1    = (const float*)d_in[10];
    const float* wh2    = (const float*)d_in[11];
    const float* wsig   = (const float*)d_in[12];

    float* out    = (float*)d_out;
    float* fusion = out;                               // [T,384]
    float* lstm   = out + (size_t)T_TOK * HID;         // [T,384]

    float *Xp, *gxp, *y1p, *x1p;
    cudaGetSymbolAddress((void**)&Xp,  g_X);
    cudaGetSymbolAddress((void**)&gxp, g_gx);
    cudaGetSymbolAddress((void**)&y1p, g_y1);
    cudaGetSymbolAddress((void**)&x1p, g_x1);

    cudaFuncSetAttribute(lstm_scan_kernel,
                         cudaFuncAttributeMaxDynamicSharedMemorySize,
                         SCAN_SMEM_BYTES);

    // 1) build X
    prepare_kernel<<<(T_TOK * 96 + 255) / 256, 256>>>(enc, forced, lens, emb, initt);

    // 2) gx = X @ W_ih^T + b_ih   [T,1536]
    sgemm_k<MODE_BIAS><<<dim3(NGATE / BN, T_TOK / BM), 256>>>(
        Xp, nullptr, W_ih, b_ih, gxp, nullptr, nullptr, NGATE, HID);

    // 3) LSTM scan -> lstm (second half of d_out)
    lstm_scan_kernel<<<128, SCAN_THREADS, SCAN_SMEM_BYTES>>>(gxp, W_hh, b_hh, lens, lstm);

    // 4) y1 = tanh(extra) @ wh2^T
    sgemm_k<MODE_TANHA><<<dim3(HID / BN, T_TOK / BM), 256>>>(
        extra, nullptr, wh2, nullptr, y1p, nullptr, nullptr, HID, HID);

    // 5) x1 = tanh(lstm) @ wh1^T
    sgemm_k<MODE_TANHA><<<dim3(HID / BN, T_TOK / BM), 256>>>(
        lstm, nullptr, wh1, nullptr, x1p, nullptr, nullptr, HID, HID);

    // 6) f = sigmoid([x1|y1] @ Wsig^T); fusion epilogue -> first half of d_out
    sgemm_k<MODE_FUSION><<<dim3(HID / BN, T_TOK / BM), 256>>>(
        x1p, y1p, wsig, nullptr, fusion, lstm, extra, HID, 2 * HID);
}

// round 4
// speedup vs baseline: 1.3857x; 1.0294x over previous
#include <cuda_runtime.h>
#include <math.h>
#include <stdint.h>

// ---------------- problem constants (fixed by setup_inputs) ----------------
#define T_TOK 32768
#define HID   384
#define NGATE 1536
#define NSEQ  16

// ---------------- scratch (static device arrays; no allocation) ------------
__device__ float g_X [(size_t)T_TOK * HID];    // [T,384] LSTM input (enc|prev)
__device__ float g_gx[(size_t)T_TOK * NGATE];  // [T,1536] input gate preacts
__device__ float g_y1[(size_t)T_TOK * HID];    // tanh(extra)@wh2^T
__device__ float g_x1[(size_t)T_TOK * HID];    // tanh(lstm)@wh1^T

__device__ __forceinline__ float sigm(float x) { return 1.f / (1.f + expf(-x)); }

// ============================================================================
// prepare: build X = [encoded | prev_label_embedding]
// ============================================================================
__global__ void prepare_kernel(const float* __restrict__ enc,
                               const int*   __restrict__ forced,
                               const int*   __restrict__ lens,
                               const float* __restrict__ emb,
                               const float* __restrict__ initt)
{
    int idx = blockIdx.x * blockDim.x + threadIdx.x;   // T*96 float4 slots
    if (idx >= T_TOK * 96) return;
    int tok = idx / 96;
    int q   = idx - tok * 96;

    float4 v;
    if (q < 64) {
        v = ((const float4*)enc)[(size_t)tok * 64 + q];
    } else {
        bool is64 = (lens[1] == 0);        // int64 layout heuristic (len!=0 always)
        bool is_start = false;
        int srt = 0;
        #pragma unroll
        for (int i = 0; i < NSEQ; i++) {
            if (tok == srt) is_start = true;
            srt += lens[is64 ? 2 * i : i];
        }
        if (is_start) {
            v = ((const float4*)initt)[q - 64];
        } else {
            int fi = forced[is64 ? 2 * (tok - 1) : (tok - 1)];
            v = ((const float4*)(emb + (size_t)fi * 128))[q - 64];
        }
    }
    ((float4*)g_X)[(size_t)tok * 96 + q] = v;
}

// ============================================================================
// SGEMM: C[M,N] = opA(A)[M,K] @ B[N,K]^T  (+bias / +fusion epilogue)
// ============================================================================
#define BM 128
#define BN 128
#define BK 16

#define MODE_BIAS   0
#define MODE_TANHA  1
#define MODE_FUSION 2

__device__ __forceinline__ float fuse_elem(float pre, float L, float Ev)
{
    float f  = 1.f / (1.f + expf(-pre));
    float x0 = tanhf(L);
    float y0 = tanhf(Ev);
    float x2 = f * x0 + L;
    float y2 = (1.f - f) * y0 + Ev;
    return f * x2 + (1.f - f) * y2;
}

template<int MODE>
__global__ __launch_bounds__(256)
void sgemm_k(const float* __restrict__ A, const float* __restrict__ A2,
             const float* __restrict__ B, const float* __restrict__ bias,
             float* __restrict__ C,
             const float* __restrict__ E1, const float* __restrict__ E2,
             int N, int K)
{
    __shared__ float As[BK][BM + 4];
    __shared__ float Bs[BK][BN + 4];

    int tid = threadIdx.x;
    int m0  = blockIdx.y * BM;
    int n0  = blockIdx.x * BN;
    int tx  = tid & 15;
    int ty  = tid >> 4;

    float acc[8][8];
    #pragma unroll
    for (int i = 0; i < 8; i++)
        #pragma unroll
        for (int j = 0; j < 8; j++) acc[i][j] = 0.f;

    for (int k0 = 0; k0 < K; k0 += BK) {
        #pragma unroll
        for (int i = 0; i < 2; i++) {
            int f  = tid + i * 256;
            int r  = f >> 2;
            int kq = f & 3;
            const float* src;
            if (MODE == MODE_FUSION) {
                src = (k0 < 384) ? (A  + (size_t)(m0 + r) * 384 + k0)
                                 : (A2 + (size_t)(m0 + r) * 384 + (k0 - 384));
            } else {
                src = A + (size_t)(m0 + r) * K + k0;
            }
            float4 v = *(const float4*)(src + kq * 4);
            if (MODE == MODE_TANHA) {
                v.x = tanhf(v.x); v.y = tanhf(v.y);
                v.z = tanhf(v.z); v.w = tanhf(v.w);
            }
            As[kq * 4 + 0][r] = v.x; As[kq * 4 + 1][r] = v.y;
            As[kq * 4 + 2][r] = v.z; As[kq * 4 + 3][r] = v.w;
        }
        #pragma unroll
        for (int i = 0; i < 2; i++) {
            int f  = tid + i * 256;
            int r  = f >> 2;
            int kq = f & 3;
            float4 v = *(const float4*)(B + (size_t)(n0 + r) * K + k0 + kq * 4);
            Bs[kq * 4 + 0][r] = v.x; Bs[kq * 4 + 1][r] = v.y;
            Bs[kq * 4 + 2][r] = v.z; Bs[kq * 4 + 3][r] = v.w;
        }
        __syncthreads();

        #pragma unroll
        for (int kk = 0; kk < BK; kk++) {
            float a[8], b[8];
            float4 a0 = *(const float4*)&As[kk][ty * 8];
            float4 a1 = *(const float4*)&As[kk][ty * 8 + 4];
            float4 b0 = *(const float4*)&Bs[kk][tx * 8];
            float4 b1 = *(const float4*)&Bs[kk][tx * 8 + 4];
            a[0]=a0.x; a[1]=a0.y; a[2]=a0.z; a[3]=a0.w;
            a[4]=a1.x; a[5]=a1.y; a[6]=a1.z; a[7]=a1.w;
            b[0]=b0.x; b[1]=b0.y; b[2]=b0.z; b[3]=b0.w;
            b[4]=b1.x; b[5]=b1.y; b[6]=b1.z; b[7]=b1.w;
            #pragma unroll
            for (int i = 0; i < 8; i++)
                #pragma unroll
                for (int j = 0; j < 8; j++)
                    acc[i][j] = fmaf(a[i], b[j], acc[i][j]);
        }
        __syncthreads();
    }

    #pragma unroll
    for (int i = 0; i < 8; i++) {
        size_t m = (size_t)(m0 + ty * 8 + i);
        #pragma unroll
        for (int q = 0; q < 2; q++) {
            int n = n0 + tx * 8 + q * 4;
            float r0 = acc[i][q * 4 + 0], r1 = acc[i][q * 4 + 1];
            float r2 = acc[i][q * 4 + 2], r3 = acc[i][q * 4 + 3];
            if (MODE == MODE_BIAS) {
                float4 bv = *(const float4*)(bias + n);
                r0 += bv.x; r1 += bv.y; r2 += bv.z; r3 += bv.w;
            }
            if (MODE == MODE_FUSION) {
                float4 L = *(const float4*)(E1 + m * 384 + n);
                float4 E = *(const float4*)(E2 + m * 384 + n);
                r0 = fuse_elem(r0, L.x, E.x); r1 = fuse_elem(r1, L.y, E.y);
                r2 = fuse_elem(r2, L.z, E.z); r3 = fuse_elem(r3, L.w, E.w);
            }
            float4 ov = make_float4(r0, r1, r2, r3);
            *(float4*)(C + m * N + n) = ov;
        }
    }
}

// ============================================================================
// LSTM scan v3: 16 sequences x 8-CTA clusters, 384 thr/CTA.
// Thread (ks=t&7, rb=t>>3): all 4 gate rows of unit rb, k-slice ks*48..+48.
//   gates i,f in registers; gates g,o in smem. shfl-reduce over 8 lanes ->
//   lane ks==0 holds all 4 gates in regs -> pointwise in-register, spread
//   over all 12 warps (no gates smem round-trip, no per-step __syncthreads
//   after the dot).
// Cross-CTA h exchange: st.async.shared::cluster with mbarrier complete_tx
//   (full[2], tx=1536B) + empty[2] (count=8) buffer-free barriers, replacing
//   barrier.cluster. One __syncthreads per step (buffer-reuse + signal order).
// ============================================================================
#define SCAN_THREADS 384
#define WS_FLOATS (24 * 384 * 4)     // 96 floats/thread of W in smem
#define HPAD 416                     // 8 chunks * 52 floats
#define MBAR_OFF ((WS_FLOATS + 2 * HPAD) * 4)
#define SCAN_SMEM_BYTES (MBAR_OFF + 64)

#define SCAN_MBAR_INIT(addr, cnt) \
    asm volatile("mbarrier.init.shared.b64 [%0], %1;" :: "r"(addr), "r"(cnt) : "memory")
#define SCAN_EXPECT_TX(addr, tx) \
    asm volatile("mbarrier.arrive.expect_tx.shared.b64 _, [%0], %1;" :: "r"(addr), "r"(tx) : "memory")
#define SCAN_ARRIVE_REMOTE(addr) \
    asm volatile("mbarrier.arrive.shared::cluster.b64 _, [%0];" :: "r"(addr) : "memory")
#define SCAN_ST_ASYNC(addr, val, mbar) \
    asm volatile("st.async.weak.shared::cluster.mbarrier::complete_tx::bytes.b32 [%0], %1, [%2];" \
                 :: "r"(addr), "r"(val), "r"(mbar) : "memory")
#define SCAN_WAIT(mbar, parity) do {                                           \
    uint32_t _done;                                                            \
    asm volatile("{\n\t.reg .pred p;\n\t"                                      \
      "mbarrier.try_wait.parity.acquire.cluster.shared::cta.b64 p, [%1], %2;\n\t" \
      "selp.b32 %0, 1, 0, p;\n\t}" : "=r"(_done) : "r"(mbar), "r"(parity) : "memory"); \
    while (!_done) {                                                           \
      asm volatile("{\n\t.reg .pred p;\n\t"                                    \
        "mbarrier.try_wait.parity.acquire.cluster.shared::cta.b64 p, [%1], %2, 0x989680;\n\t" \
        "selp.b32 %0, 1, 0, p;\n\t}" : "=r"(_done) : "r"(mbar), "r"(parity) : "memory"); \
    }                                                                          \
} while (0)

__global__ void __cluster_dims__(8, 1, 1) __launch_bounds__(SCAN_THREADS, 1)
lstm_scan_kernel(const float* __restrict__ gx, const float* __restrict__ W_hh,
                 const float* __restrict__ b_hh, const int* __restrict__ lens,
                 float* __restrict__ lstm)
{
    extern __shared__ float sm[];
    float4* Ws4   = (float4*)sm;          // [24][384] float4 (gates g,o)
    float*  h_pad = sm + WS_FLOATS;       // [2][HPAD]

    uint32_t smem_base;
    asm("{ .reg .u64 u; cvta.to.shared.u64 u, %1; cvt.u32.u64 %0, u; }"
        : "=r"(smem_base) : "l"(sm));
    uint32_t hpad_base = smem_base + WS_FLOATS * 4;
    uint32_t mbar_base = smem_base + MBAR_OFF;   // full0@0 full1@8 empty0@16 empty1@24

    int t = threadIdx.x;
    uint32_t rank;
    asm("mov.u32 %0, %%cluster_ctarank;" : "=r"(rank));
    int seq = blockIdx.x >> 3;

    bool is64 = (lens[1] == 0);
    int start = 0;
    for (int i = 0; i < seq; i++) start += lens[is64 ? 2 * i : i];
    int len = lens[is64 ? 2 * seq : seq];

    int ks    = t & 7;        // k-slice: k in [ks*48, ks*48+48)
    int rb    = t >> 3;       // hidden unit (local 0..47)
    int kbase = ks * 48;
    bool owner = (ks == 0);

    // ---- stage W: gates i,f (rows) -> registers; gates g,o -> smem ----
    float4 wi[12], wf[12];
    #pragma unroll
    for (int g = 0; g < 4; g++) {
        int grow = g * HID + (int)rank * 48 + rb;
        const float4* src = (const float4*)(W_hh + (size_t)grow * HID + kbase);
        if (g == 0) {
            #pragma unroll
            for (int j = 0; j < 12; j++) wi[j] = src[j];
        } else if (g == 1) {
            #pragma unroll
            for (int j = 0; j < 12; j++) wf[j] = src[j];
        } else {
            #pragma unroll
            for (int j = 0; j < 12; j++) Ws4[((g - 2) * 12 + j) * 384 + t] = src[j];
        }
    }

    // ---- owner-lane state ----
    float c = 0.f, bh0 = 0.f, bh1 = 0.f, bh2 = 0.f, bh3 = 0.f;
    const float* gxp  = gx;
    float*       lout = lstm;
    if (owner) {
        int u = (int)rank * 48 + rb;
        bh0 = b_hh[u];            bh1 = b_hh[HID + u];
        bh2 = b_hh[2 * HID + u];  bh3 = b_hh[3 * HID + u];
        gxp  = gx   + (size_t)start * NGATE + u;
        lout = lstm + (size_t)start * HID   + u;
    }

    // ---- peer base addresses (h_pad and mbar block in each cluster CTA) ----
    uint32_t peer_h[8], peer_m[8];
    #pragma unroll
    for (int r = 0; r < 8; r++) {
        asm("mapa.shared::cluster.u32 %0, %1, %2;" : "=r"(peer_h[r]) : "r"(hpad_base), "r"(r));
        asm("mapa.shared::cluster.u32 %0, %1, %2;" : "=r"(peer_m[r]) : "r"(mbar_base), "r"(r));
    }

    // ---- init: mbars + zero h buffers, publish to cluster ----
    if (t == 0) {
        SCAN_MBAR_INIT(mbar_base + 0, 1);    // full0 (tx-based)
        SCAN_MBAR_INIT(mbar_base + 8, 1);    // full1
        SCAN_MBAR_INIT(mbar_base + 16, 8);   // empty0 (8 CTA arrives)
        SCAN_MBAR_INIT(mbar_base + 24, 8);   // empty1
        SCAN_EXPECT_TX(mbar_base + 0, 1536); // pre-arm phase 0 of both fulls
        SCAN_EXPECT_TX(mbar_base + 8, 1536);
    }
    for (int i = t; i < 2 * HPAD; i += SCAN_THREADS) h_pad[i] = 0.f;
    __syncthreads();
    asm volatile("barrier.cluster.arrive.aligned;" ::: "memory");
    asm volatile("barrier.cluster.wait.aligned;" ::: "memory");

    int phF0 = 0, phF1 = 0, phE0 = 0, phE1 = 0;

    for (int step = 0; step < len; step++) {
        // gx for this step (owner lanes) — issue before any waiting
        float g0 = 0.f, g1 = 0.f, g2 = 0.f, g3 = 0.f;
        if (owner) {
            const float* gp = gxp + (size_t)step * NGATE;
            g0 = __ldg(gp);
            g1 = __ldg(gp + HID);
            g2 = __ldg(gp + 2 * HID);
            g3 = __ldg(gp + 3 * HID);
        }
        // all local threads done with previous step (incl. reads of old buffer)
        __syncthreads();

        if (step > 0) {
            // t0: tell all peers the buffer we read last step is free again
            if (t == 0) {
                int eb = (step - 1) & 1;
                #pragma unroll
                for (int r = 0; r < 8; r++)
                    SCAN_ARRIVE_REMOTE(peer_m[r] + 16 + eb * 8);
            }
            // wait for this step's h (full barrier of buffer step&1)
            int b = step & 1;
            if (b) { SCAN_WAIT(mbar_base + 8, phF1); phF1 ^= 1; }
            else   { SCAN_WAIT(mbar_base + 0, phF0); phF0 ^= 1; }
        }

        // ---- dot: 4 gate rows of unit rb over 48 k-elems ----
        int par = step & 1;
        const float4* h4 = (const float4*)(h_pad + par * HPAD + ks * 52);
        float a0 = 0.f, a1 = 0.f, a2 = 0.f, a3 = 0.f;
        #pragma unroll
        for (int j = 0; j < 12; j++) {
            float4 hv = h4[j];
            float4 v0 = wi[j];
            float4 v1 = wf[j];
            float4 v2 = Ws4[j * 384 + t];
            float4 v3 = Ws4[(12 + j) * 384 + t];
            a0 = fmaf(v0.x, hv.x, a0); a0 = fmaf(v0.y, hv.y, a0);
            a0 = fmaf(v0.z, hv.z, a0); a0 = fmaf(v0.w, hv.w, a0);
            a1 = fmaf(v1.x, hv.x, a1); a1 = fmaf(v1.y, hv.y, a1);
            a1 = fmaf(v1.z, hv.z, a1); a1 = fmaf(v1.w, hv.w, a1);
            a2 = fmaf(v2.x, hv.x, a2); a2 = fmaf(v2.y, hv.y, a2);
            a2 = fmaf(v2.z, hv.z, a2); a2 = fmaf(v2.w, hv.w, a2);
            a3 = fmaf(v3.x, hv.x, a3); a3 = fmaf(v3.y, hv.y, a3);
            a3 = fmaf(v3.z, hv.z, a3); a3 = fmaf(v3.w, hv.w, a3);
        }
        // reduce over the 8 k-slices (lane bits 0..2)
        a0 += __shfl_xor_sync(0xffffffffu, a0, 1);
        a1 += __shfl_xor_sync(0xffffffffu, a1, 1);
        a2 += __shfl_xor_sync(0xffffffffu, a2, 1);
        a3 += __shfl_xor_sync(0xffffffffu, a3, 1);
        a0 += __shfl_xor_sync(0xffffffffu, a0, 2);
        a1 += __shfl_xor_sync(0xffffffffu, a1, 2);
        a2 += __shfl_xor_sync(0xffffffffu, a2, 2);
        a3 += __shfl_xor_sync(0xffffffffu, a3, 2);
        a0 += __shfl_xor_sync(0xffffffffu, a0, 4);
        a1 += __shfl_xor_sync(0xffffffffu, a1, 4);
        a2 += __shfl_xor_sync(0xffffffffu, a2, 4);
        a3 += __shfl_xor_sync(0xffffffffu, a3, 4);

        if (owner) {
            float gi = a0 + g0 + bh0;
            float gf = a1 + g1 + bh1;
            float gg = a2 + g2 + bh2;
            float go = a3 + g3 + bh3;
            c = sigm(gf) * c + sigm(gi) * tanhf(gg);
            float h = sigm(go) * tanhf(c);
            lout[(size_t)step * HID] = h;

            if (step < len - 1) {
                int bw = (step + 1) & 1;
                // wait until every CTA finished reading buffer bw (step-1 dot)
                if (step >= 1) {
                    if (bw) { SCAN_WAIT(mbar_base + 24, phE1); phE1 ^= 1; }
                    else    { SCAN_WAIT(mbar_base + 16, phE0); phE0 ^= 1; }
                }
                // t0 re-arms the full barrier just consumed (next use = step+2)
                // BEFORE its own sends: remote senders to it causally depend on
                // t0's bytes below, so expect_tx precedes every complete_tx.
                if (t == 0 && step >= 1 && step <= len - 3)
                    SCAN_EXPECT_TX(mbar_base + (step & 1) * 8, 1536);
                // push h to all 8 CTAs' buffer bw with tx accounting
                uint32_t off = (uint32_t)(bw * HPAD + (int)rank * 52 + rb) * 4;
                uint32_t hb  = __float_as_uint(h);
                #pragma unroll
                for (int r = 0; r < 8; r++)
                    SCAN_ST_ASYNC(peer_h[r] + off, hb, peer_m[r] + bw * 8);
            }
        }
    }

    asm volatile("barrier.cluster.arrive.aligned;" ::: "memory");
    asm volatile("barrier.cluster.wait.aligned;" ::: "memory");
}

// ============================================================================
// launch
// ============================================================================
extern "C" void kernel_launch(void* const* d_in, const int* in_sizes, int n_in,
                              void* d_out, int out_size)
{
    const float* enc    = (const float*)d_in[0];
    const float* extra  = (const float*)d_in[1];
    const int*   forced = (const int*)  d_in[2];
    const int*   lens   = (const int*)  d_in[3];
    const float* emb    = (const float*)d_in[4];
    const float* initt  = (const float*)d_in[5];
    const float* W_ih   = (const float*)d_in[6];
    const float* W_hh   = (const float*)d_in[7];
    const float* b_ih   = (const float*)d_in[8];
    const float* b_hh   = (const float*)d_in[9];
    const float* wh1    = (const float*)d_in[10];
    const float* wh2    = (const float*)d_in[11];
    const float* wsig   = (const float*)d_in[12];

    float* out    = (float*)d_out;
    float* fusion = out;                               // [T,384]
    float* lstm   = out + (size_t)T_TOK * HID;         // [T,384]

    float *Xp, *gxp, *y1p, *x1p;
    cudaGetSymbolAddress((void**)&Xp,  g_X);
    cudaGetSymbolAddress((void**)&gxp, g_gx);
    cudaGetSymbolAddress((void**)&y1p, g_y1);
    cudaGetSymbolAddress((void**)&x1p, g_x1);

    cudaFuncSetAttribute(lstm_scan_kernel,
                         cudaFuncAttributeMaxDynamicSharedMemorySize,
                         SCAN_SMEM_BYTES);

    // 1) build X
    prepare_kernel<<<(T_TOK * 96 + 255) / 256, 256>>>(enc, forced, lens, emb, initt);

    // 2) gx = X @ W_ih^T + b_ih   [T,1536]
    sgemm_k<MODE_BIAS><<<dim3(NGATE / BN, T_TOK / BM), 256>>>(
        Xp, nullptr, W_ih, b_ih, gxp, nullptr, nullptr, NGATE, HID);

    // 3) LSTM scan -> lstm (second half of d_out)
    lstm_scan_kernel<<<128, SCAN_THREADS, SCAN_SMEM_BYTES>>>(gxp, W_hh, b_hh, lens, lstm);

    // 4) y1 = tanh(extra) @ wh2^T
    sgemm_k<MODE_TANHA><<<dim3(HID / BN, T_TOK / BM), 256>>>(
        extra, nullptr, wh2, nullptr, y1p, nullptr, nullptr, HID, HID);

    // 5) x1 = tanh(lstm) @ wh1^T
    sgemm_k<MODE_TANHA><<<dim3(HID / BN, T_TOK / BM), 256>>>(
        lstm, nullptr, wh1, nullptr, x1p, nullptr, nullptr, HID, HID);

    // 6) f = sigmoid([x1|y1] @ Wsig^T); fusion epilogue -> first half of d_out
    sgemm_k<MODE_FUSION><<<dim3(HID / BN, T_TOK / BM), 256>>>(
        x1p, y1p, wsig, nullptr, fusion, lstm, extra, HID, 2 * HID);
}